// round 2
// baseline (speedup 1.0000x reference)
#include <cuda_runtime.h>
#include <cuda_bf16.h>
#include <cstdint>
#include <cfloat>

// Problem constants
#define BATCH   16384
#define NWIN    32
#define DIM     64
#define KCODES  512
#define WINDOWS (BATCH * NWIN)          // 524288
#define TPB     512                      // threads per block = windows per block
#define NCTA    (WINDOWS / TPB)          // 1024
#define ZQ_ELEMS ((long long)WINDOWS * DIM)  // 33554432

// Device-global scratch (no allocations allowed in kernel_launch)
__device__ double g_loss_sum;
__device__ int    g_counts[KCODES];
__device__ float  g_norms[KCODES];

// ---------- packed f32x2 helpers (Blackwell FFMA2 via PTX) ----------
__device__ __forceinline__ unsigned long long pack2(float a, float b) {
    unsigned long long r;
    asm("mov.b64 %0, {%1, %2};" : "=l"(r)
        : "r"(__float_as_uint(a)), "r"(__float_as_uint(b)));
    return r;
}
__device__ __forceinline__ float2 unpack2(unsigned long long p) {
    unsigned int lo, hi;
    asm("mov.b64 {%0, %1}, %2;" : "=r"(lo), "=r"(hi) : "l"(p));
    return make_float2(__uint_as_float(lo), __uint_as_float(hi));
}
#define FMA2(acc, a, b) \
    asm("fma.rn.f32x2 %0, %1, %2, %0;" : "+l"(acc) : "l"(a), "l"(b))

__device__ __forceinline__ float sumpair(unsigned long long p) {
    float2 v = unpack2(p);
    return v.x + v.y;
}

// ---------- init: zero accumulators, compute codebook norms ----------
__global__ void vq_init_kernel(const float* __restrict__ cb) {
    int t = threadIdx.x;  // 512 threads
    if (t == 0) g_loss_sum = 0.0;
    g_counts[t] = 0;
    const float4* r = (const float4*)(cb + (size_t)t * DIM);
    float s = 0.f;
#pragma unroll
    for (int i = 0; i < DIM / 4; i++) {
        float4 v = r[i];
        s = fmaf(v.x, v.x, s);
        s = fmaf(v.y, v.y, s);
        s = fmaf(v.z, v.z, s);
        s = fmaf(v.w, v.w, s);
    }
    g_norms[t] = s;
}

// ---------- main kernel ----------
// smem layout (floats): [0,32768) codebook, [32768,33280) norms,
//                       [33280,33792) idx (int), [33792,34304) reduce
#define SMEM_FLOATS 34304
#define SMEM_BYTES  (SMEM_FLOATS * 4)

__global__ void __launch_bounds__(TPB)
vq_main_kernel(const float* __restrict__ ze, const float* __restrict__ cb,
               float* __restrict__ out, int idx_off, long long zq_off,
               long long scal_off) {
    extern __shared__ float sm[];
    float* scb   = sm;                       // 512 x 64
    float* snorm = sm + 32768;               // 512
    int*   sidx  = (int*)(sm + 33280);       // 512
    float* sred  = sm + 33792;               // 512

    const int tid = threadIdx.x;

    // cooperative codebook stage (global -> smem), vectorized
    {
        float4*       d4 = (float4*)scb;
        const float4* s4 = (const float4*)cb;
#pragma unroll 4
        for (int i = tid; i < KCODES * DIM / 4; i += TPB) d4[i] = s4[i];
    }
    snorm[tid] = g_norms[tid];
    __syncthreads();

    const int g = blockIdx.x * TPB + tid;  // global window id

    // load this thread's z window, packed as 32 f32x2
    unsigned long long zp[DIM / 2];
    {
        const float4* z4 = (const float4*)(ze + (size_t)g * DIM);
#pragma unroll
        for (int i = 0; i < DIM / 4; i++) {
            float4 v = z4[i];
            zp[2 * i]     = pack2(v.x, v.y);
            zp[2 * i + 1] = pack2(v.z, v.w);
        }
    }

    // distance scan: score_k = ||e_k||^2 - 2 z.e_k   (same ordering as ref)
    float best = FLT_MAX;
    int   bidx = 0;
    const ulonglong2* cbp = (const ulonglong2*)scb;  // 16 ulonglong2 per code row

#pragma unroll 1
    for (int k0 = 0; k0 < KCODES; k0 += 4) {
        unsigned long long a0 = 0ull, a1 = 0ull, a2 = 0ull, a3 = 0ull;
        const ulonglong2* r0 = cbp + (size_t)(k0 + 0) * 16;
        const ulonglong2* r1 = cbp + (size_t)(k0 + 1) * 16;
        const ulonglong2* r2 = cbp + (size_t)(k0 + 2) * 16;
        const ulonglong2* r3 = cbp + (size_t)(k0 + 3) * 16;
#pragma unroll
        for (int i = 0; i < 16; i++) {
            ulonglong2 c0 = r0[i];
            ulonglong2 c1 = r1[i];
            ulonglong2 c2 = r2[i];
            ulonglong2 c3 = r3[i];
            FMA2(a0, zp[2 * i], c0.x); FMA2(a0, zp[2 * i + 1], c0.y);
            FMA2(a1, zp[2 * i], c1.x); FMA2(a1, zp[2 * i + 1], c1.y);
            FMA2(a2, zp[2 * i], c2.x); FMA2(a2, zp[2 * i + 1], c2.y);
            FMA2(a3, zp[2 * i], c3.x); FMA2(a3, zp[2 * i + 1], c3.y);
        }
        float s0 = fmaf(-2.f, sumpair(a0), snorm[k0 + 0]);
        float s1 = fmaf(-2.f, sumpair(a1), snorm[k0 + 1]);
        float s2 = fmaf(-2.f, sumpair(a2), snorm[k0 + 2]);
        float s3 = fmaf(-2.f, sumpair(a3), snorm[k0 + 3]);
        if (s0 < best) { best = s0; bidx = k0 + 0; }
        if (s1 < best) { best = s1; bidx = k0 + 1; }
        if (s2 < best) { best = s2; bidx = k0 + 2; }
        if (s3 < best) { best = s3; bidx = k0 + 3; }
    }

    sidx[tid] = bidx;
    atomicAdd(&g_counts[bidx], 1);
    if (idx_off >= 0) out[(long long)idx_off + g] = (float)bidx;

    // exact fp32 loss recompute: ||e_bidx - z||^2
    float lsum = 0.f;
    {
        const float* crow = scb + bidx * DIM;
#pragma unroll
        for (int i = 0; i < DIM / 2; i++) {
            float2 zz = unpack2(zp[i]);
            float d0 = crow[2 * i]     - zz.x;
            float d1 = crow[2 * i + 1] - zz.y;
            lsum = fmaf(d0, d0, lsum);
            lsum = fmaf(d1, d1, lsum);
        }
    }
    sred[tid] = lsum;
    __syncthreads();
#pragma unroll
    for (int s = TPB / 2; s > 0; s >>= 1) {
        if (tid < s) sred[tid] += sred[tid + s];
        __syncthreads();
    }
    if (tid == 0) atomicAdd(&g_loss_sum, (double)sred[0]);

    // cooperative, coalesced zq write (gather from smem codebook)
    if (zq_off >= 0) {
        const long long base = (long long)blockIdx.x * TPB * DIM;
#pragma unroll 4
        for (int e = tid; e < TPB * DIM; e += TPB) {
            int w = e >> 6;
            int d = e & 63;
            out[zq_off + base + e] = scb[(sidx[w] << 6) + d];
        }
    }
}

// ---------- finalize: entropy + loss scalars ----------
__global__ void vq_finalize_kernel(float* __restrict__ out, long long scal_off) {
    __shared__ double sd[KCODES];
    int t = threadIdx.x;  // 512
    float p = (float)g_counts[t] / 10.0f;
    float term = p * logf(p + 1e-10f);
    sd[t] = (double)term;
    __syncthreads();
#pragma unroll
    for (int s = KCODES / 2; s > 0; s >>= 1) {
        if (t < s) sd[t] += sd[t + s];
        __syncthreads();
    }
    if (t == 0 && scal_off >= 0) {
        float loss = (float)(g_loss_sum / (double)ZQ_ELEMS);
        out[scal_off + 0] = loss;       // vq_e_loss
        out[scal_off + 1] = loss;       // vq_commit_loss (identical forward value)
        out[scal_off + 2] = (float)sd[0];
    }
}

extern "C" void kernel_launch(void* const* d_in, const int* in_sizes, int n_in,
                              void* d_out, int out_size) {
    const float* ze = (const float*)d_in[0];   // [B, NW*D] fp32
    const float* cb = (const float*)d_in[1];   // [K, D]    fp32
    float* out = (float*)d_out;

    // Output contract (best guess, branch defensively on out_size):
    // flattened concat of reference return tuple, cast to float32:
    //   indices [B*NW] | zq [B*NW*D] | vq_e_loss | vq_commit_loss | entropy
    long long idx_off = 0, zq_off = WINDOWS, scal_off = WINDOWS + ZQ_ELEMS;
    long long full = (long long)WINDOWS + ZQ_ELEMS + 3;
    if ((long long)out_size == full) {
        ;  // standard layout
    } else if ((long long)out_size == ZQ_ELEMS) {
        idx_off = -1; zq_off = 0; scal_off = -1;
    } else if ((long long)out_size == ZQ_ELEMS + 3) {
        idx_off = -1; zq_off = 0; scal_off = ZQ_ELEMS;
    } else if (out_size == WINDOWS) {
        idx_off = 0; zq_off = -1; scal_off = -1;
    } else if ((long long)out_size == (long long)WINDOWS + ZQ_ELEMS) {
        idx_off = 0; zq_off = WINDOWS; scal_off = -1;
    }
    // else: keep full-layout offsets (will write within whatever is valid)

    cudaFuncSetAttribute(vq_main_kernel,
                         cudaFuncAttributeMaxDynamicSharedMemorySize, SMEM_BYTES);

    vq_init_kernel<<<1, KCODES>>>(cb);
    vq_main_kernel<<<NCTA, TPB, SMEM_BYTES>>>(ze, cb, out,
                                              (int)idx_off, zq_off, scal_off);
    vq_finalize_kernel<<<1, KCODES>>>(out, scal_off);
}

// round 6
// speedup vs baseline: 1.2602x; 1.2602x over previous
#include <cuda_runtime.h>
#include <cuda_bf16.h>
#include <mma.h>
#include <cstdint>
#include <cfloat>

using namespace nvcuda;

// ---------------- problem constants ----------------
#define BATCH   16384
#define NWIN    32
#define DIM     64
#define KPAD    80                            // 64 data + 16 norm/pad block
#define KCODES  512
#define WINDOWS (BATCH * NWIN)                // 524288
#define ZQ_ELEMS ((long long)WINDOWS * DIM)   // 33554432
#define MTILE   128
#define NTILES  (WINDOWS / MTILE)             // 4096
#define GRID    148
#define TPB     128
#define CH_N    32                            // codes per epilogue chunk
#define CH_LD   36                            // chunk buffer leading dim (floats)
#define NCHUNK  (KCODES / CH_N)               // 16

// ---------------- device globals (no allocs allowed) ----------------
__device__ double g_loss_sum;
__device__ int    g_counts[KCODES];
__device__ float  g_norms[KCODES];
__device__ __nv_bfloat16 g_cb_hi[KCODES * KPAD];  // rows: [-2e]_hi | nh nl 0...
__device__ __nv_bfloat16 g_cb_lo[KCODES * KPAD];  // rows: [-2e]_lo | 0...

// ---------------- smem layout (bytes) ----------------
#define A_HI_OFF   0                          // 128 x 80 bf16 = 20480
#define A_LO_OFF   20480
#define B_HI_OFF   40960                      // 512 x 80 bf16 = 81920
#define B_LO_OFF   122880
#define CHUNK_OFF  204800                     // 128 x 36 f32 = 18432
#define HIST_OFF   223232                     // 512 i32
#define RED_OFF    225280                     // 8 f32
#define SMEM_BYTES 225312

// ---------------- prep: norms + scaled/split codebook ----------------
__global__ void vq_prep_kernel(const float* __restrict__ cb) {
    int k = threadIdx.x;  // 512
    if (k == 0) g_loss_sum = 0.0;
    g_counts[k] = 0;
    float s = 0.f;
#pragma unroll
    for (int d = 0; d < DIM; d++) {
        float x = cb[k * DIM + d];
        s = fmaf(x, x, s);
        float b = -2.f * x;
        __nv_bfloat16 h = __float2bfloat16(b);
        g_cb_hi[k * KPAD + d] = h;
        g_cb_lo[k * KPAD + d] = __float2bfloat16(b - __bfloat162float(h));
    }
    g_norms[k] = s;
    // padded block: norm split hi/lo multiplied by A's constant [1,1,0,...]
    __nv_bfloat16 nh = __float2bfloat16(s);
    __nv_bfloat16 nl = __float2bfloat16(s - __bfloat162float(nh));
    g_cb_hi[k * KPAD + DIM]     = nh;
    g_cb_hi[k * KPAD + DIM + 1] = nl;
#pragma unroll
    for (int d = DIM + 2; d < KPAD; d++) g_cb_hi[k * KPAD + d] = __float2bfloat16(0.f);
#pragma unroll
    for (int d = DIM; d < KPAD; d++) g_cb_lo[k * KPAD + d] = __float2bfloat16(0.f);
}

// ---------------- main persistent WMMA kernel ----------------
__global__ void __launch_bounds__(TPB, 1)
vq_mma_kernel(const float* __restrict__ ze, const float* __restrict__ cb,
              float* __restrict__ out, long long idx_off, long long zq_off) {
    extern __shared__ char sm[];
    __nv_bfloat16* sAh = (__nv_bfloat16*)(sm + A_HI_OFF);
    __nv_bfloat16* sAl = (__nv_bfloat16*)(sm + A_LO_OFF);
    __nv_bfloat16* sBh = (__nv_bfloat16*)(sm + B_HI_OFF);
    __nv_bfloat16* sBl = (__nv_bfloat16*)(sm + B_LO_OFF);
    float* schunk = (float*)(sm + CHUNK_OFF);
    int*   shist  = (int*)(sm + HIST_OFF);
    float* sred   = (float*)(sm + RED_OFF);

    const int tid = threadIdx.x;
    const int wid = tid >> 5;

    // one-time: histogram zero, codebook stage, A pad-block constants
    for (int k = tid; k < KCODES; k += TPB) shist[k] = 0;
    {
        const uint4* gh = (const uint4*)g_cb_hi;  // 512*80*2/16 = 5120 chunks
        uint4* dh = (uint4*)sBh;
        const uint4* gl = (const uint4*)g_cb_lo;
        uint4* dl = (uint4*)sBl;
#pragma unroll 4
        for (int j = tid; j < KCODES * KPAD * 2 / 16; j += TPB) {
            dh[j] = gh[j];
            dl[j] = gl[j];
        }
    }
    {
        // A rows: constant tail [1,1,0...] for hi, zeros for lo
        __nv_bfloat16 one = __float2bfloat16(1.f);
        __nv_bfloat16 zro = __float2bfloat16(0.f);
#pragma unroll
        for (int d = DIM; d < KPAD; d++) {
            sAh[tid * KPAD + d] = (d < DIM + 2) ? one : zro;
            sAl[tid * KPAD + d] = zro;
        }
    }
    __syncthreads();

    float lsum = 0.f;
    const int m0 = wid * 32;  // this warp's M origin within the tile

    for (int tile = blockIdx.x; tile < NTILES; tile += gridDim.x) {
        const long long w = (long long)tile * MTILE + tid;

        // ---- load z row, split hi/lo into A tile ----
        {
            const float4* zp = (const float4*)(ze + w * DIM);
#pragma unroll
            for (int i = 0; i < 8; i++) {  // 8 bf16 (16B) per iteration
                float4 v0 = zp[2 * i], v1 = zp[2 * i + 1];
                float x[8] = {v0.x, v0.y, v0.z, v0.w, v1.x, v1.y, v1.z, v1.w};
                uint32_t hw[4], lw[4];
#pragma unroll
                for (int q = 0; q < 4; q++) {
                    __nv_bfloat16 h0 = __float2bfloat16(x[2 * q]);
                    __nv_bfloat16 h1 = __float2bfloat16(x[2 * q + 1]);
                    __nv_bfloat162 hh = __halves2bfloat162(h0, h1);
                    __nv_bfloat162 ll = __halves2bfloat162(
                        __float2bfloat16(x[2 * q] - __bfloat162float(h0)),
                        __float2bfloat16(x[2 * q + 1] - __bfloat162float(h1)));
                    hw[q] = *(uint32_t*)&hh;
                    lw[q] = *(uint32_t*)&ll;
                }
                *(uint4*)(sAh + tid * KPAD + i * 8) = make_uint4(hw[0], hw[1], hw[2], hw[3]);
                *(uint4*)(sAl + tid * KPAD + i * 8) = make_uint4(lw[0], lw[1], lw[2], lw[3]);
            }
        }
        __syncthreads();

        // ---- cache A fragments (per warp: rows m0..m0+31) ----
        wmma::fragment<wmma::matrix_a, 16, 16, 16, __nv_bfloat16, wmma::row_major> aH[2][5], aL[2][4];
#pragma unroll
        for (int mt = 0; mt < 2; mt++) {
#pragma unroll
            for (int kb = 0; kb < 5; kb++)
                wmma::load_matrix_sync(aH[mt][kb], sAh + (m0 + mt * 16) * KPAD + kb * 16, KPAD);
#pragma unroll
            for (int kb = 0; kb < 4; kb++)
                wmma::load_matrix_sync(aL[mt][kb], sAl + (m0 + mt * 16) * KPAD + kb * 16, KPAD);
        }

        // ---- N chunks: MMA -> smem scores -> per-thread argmin ----
        float best = FLT_MAX, best2 = FLT_MAX;
        int   bidx = 0,       bidx2 = 0;

#pragma unroll 1
        for (int ch = 0; ch < NCHUNK; ch++) {
            wmma::fragment<wmma::accumulator, 16, 16, 16, float> acc[2][2];
#pragma unroll
            for (int mt = 0; mt < 2; mt++)
#pragma unroll
                for (int nt = 0; nt < 2; nt++) wmma::fill_fragment(acc[mt][nt], 0.f);

            const int n0 = ch * CH_N;
#pragma unroll
            for (int kb = 0; kb < 4; kb++) {
                wmma::fragment<wmma::matrix_b, 16, 16, 16, __nv_bfloat16, wmma::col_major> bH[2], bL[2];
#pragma unroll
                for (int nt = 0; nt < 2; nt++) {
                    wmma::load_matrix_sync(bH[nt], sBh + (n0 + nt * 16) * KPAD + kb * 16, KPAD);
                    wmma::load_matrix_sync(bL[nt], sBl + (n0 + nt * 16) * KPAD + kb * 16, KPAD);
                }
#pragma unroll
                for (int mt = 0; mt < 2; mt++)
#pragma unroll
                    for (int nt = 0; nt < 2; nt++) {
                        wmma::mma_sync(acc[mt][nt], aH[mt][kb], bH[nt], acc[mt][nt]);
                        wmma::mma_sync(acc[mt][nt], aH[mt][kb], bL[nt], acc[mt][nt]);
                        wmma::mma_sync(acc[mt][nt], aL[mt][kb], bH[nt], acc[mt][nt]);
                    }
            }
            {   // kb=4: norm block, hi only
                wmma::fragment<wmma::matrix_b, 16, 16, 16, __nv_bfloat16, wmma::col_major> bH[2];
#pragma unroll
                for (int nt = 0; nt < 2; nt++)
                    wmma::load_matrix_sync(bH[nt], sBh + (n0 + nt * 16) * KPAD + 4 * 16, KPAD);
#pragma unroll
                for (int mt = 0; mt < 2; mt++)
#pragma unroll
                    for (int nt = 0; nt < 2; nt++)
                        wmma::mma_sync(acc[mt][nt], aH[mt][4], bH[nt], acc[mt][nt]);
            }

            // stash chunk scores, then every thread scans its own window-row
#pragma unroll
            for (int mt = 0; mt < 2; mt++)
#pragma unroll
                for (int nt = 0; nt < 2; nt++)
                    wmma::store_matrix_sync(schunk + (m0 + mt * 16) * CH_LD + nt * 16,
                                            acc[mt][nt], CH_LD, wmma::mem_row_major);
            __syncthreads();

            const float* rowp = schunk + tid * CH_LD;
#pragma unroll
            for (int j = 0; j < CH_N; j++) {
                float s = rowp[j];
                int   k = n0 + j;
                if (s < best) { best2 = best; bidx2 = bidx; best = s; bidx = k; }
                else if (s < best2) { best2 = s; bidx2 = k; }
            }
            __syncthreads();
        }

        // ---- exact fp32 rescue on near-ties ----
        float zr[DIM];
        {
            const float4* zp = (const float4*)(ze + w * DIM);
#pragma unroll
            for (int i = 0; i < DIM / 4; i++) {
                float4 v = zp[i];
                zr[4 * i] = v.x; zr[4 * i + 1] = v.y;
                zr[4 * i + 2] = v.z; zr[4 * i + 3] = v.w;
            }
        }
        if (best2 - best < 0.0078125f) {
            float d1 = 0.f, d2 = 0.f;
            const float4* c1 = (const float4*)(cb + (size_t)bidx * DIM);
            const float4* c2 = (const float4*)(cb + (size_t)bidx2 * DIM);
#pragma unroll
            for (int i = 0; i < DIM / 4; i++) {
                float4 v1 = c1[i], v2 = c2[i];
                d1 = fmaf(v1.x, zr[4 * i], d1); d1 = fmaf(v1.y, zr[4 * i + 1], d1);
                d1 = fmaf(v1.z, zr[4 * i + 2], d1); d1 = fmaf(v1.w, zr[4 * i + 3], d1);
                d2 = fmaf(v2.x, zr[4 * i], d2); d2 = fmaf(v2.y, zr[4 * i + 1], d2);
                d2 = fmaf(v2.z, zr[4 * i + 2], d2); d2 = fmaf(v2.w, zr[4 * i + 3], d2);
            }
            float s1 = fmaf(-2.f, d1, g_norms[bidx]);
            float s2 = fmaf(-2.f, d2, g_norms[bidx2]);
            if (s2 < s1 || (s2 == s1 && bidx2 < bidx)) bidx = bidx2;
        }

        out[idx_off + w] = (float)bidx;
        atomicAdd(&shist[bidx], 1);

        // ---- exact loss + zq write (fp32 codebook, L2-resident) ----
        {
            const float4* crow = (const float4*)(cb + (size_t)bidx * DIM);
            float4* zqp = (float4*)(out + zq_off + w * DIM);
#pragma unroll
            for (int i = 0; i < DIM / 4; i++) {
                float4 v = crow[i];
                float e0 = v.x - zr[4 * i],     e1 = v.y - zr[4 * i + 1];
                float e2 = v.z - zr[4 * i + 2], e3 = v.w - zr[4 * i + 3];
                lsum = fmaf(e0, e0, lsum); lsum = fmaf(e1, e1, lsum);
                lsum = fmaf(e2, e2, lsum); lsum = fmaf(e3, e3, lsum);
                zqp[i] = v;
            }
        }
        __syncthreads();  // A tile safe to rewrite next iteration
    }

    // ---- CTA reductions: loss + histogram flush ----
#pragma unroll
    for (int o = 16; o > 0; o >>= 1) lsum += __shfl_xor_sync(0xFFFFFFFF, lsum, o);
    if ((tid & 31) == 0) sred[wid] = lsum;
    __syncthreads();
    if (tid == 0) {
        double t = (double)sred[0] + (double)sred[1] + (double)sred[2] + (double)sred[3];
        atomicAdd(&g_loss_sum, t);
    }
    for (int k = tid; k < KCODES; k += TPB)
        if (shist[k]) atomicAdd(&g_counts[k], shist[k]);
}

// ---------------- finalize: entropy + loss scalars ----------------
__global__ void vq_finalize_kernel(float* __restrict__ out, long long scal_off) {
    __shared__ double sd[KCODES];
    int t = threadIdx.x;  // 512
    float p = (float)g_counts[t] / 10.0f;
    sd[t] = (double)(p * logf(p + 1e-10f));
    __syncthreads();
#pragma unroll
    for (int s = KCODES / 2; s > 0; s >>= 1) {
        if (t < s) sd[t] += sd[t + s];
        __syncthreads();
    }
    if (t == 0 && scal_off >= 0) {
        float loss = (float)(g_loss_sum / (double)ZQ_ELEMS);
        out[scal_off + 0] = loss;
        out[scal_off + 1] = loss;
        out[scal_off + 2] = (float)sd[0];
    }
}

extern "C" void kernel_launch(void* const* d_in, const int* in_sizes, int n_in,
                              void* d_out, int out_size) {
    const float* ze = (const float*)d_in[0];
    const float* cb = (const float*)d_in[1];
    float* out = (float*)d_out;

    long long idx_off = 0, zq_off = WINDOWS, scal_off = (long long)WINDOWS + ZQ_ELEMS;

    static bool attr_set = false;
    if (!attr_set) {
        cudaFuncSetAttribute(vq_mma_kernel,
                             cudaFuncAttributeMaxDynamicSharedMemorySize, SMEM_BYTES);
        attr_set = true;
    }

    vq_prep_kernel<<<1, KCODES>>>(cb);
    vq_mma_kernel<<<GRID, TPB, SMEM_BYTES>>>(ze, cb, out, idx_off, zq_off);
    vq_finalize_kernel<<<1, KCODES>>>(out, scal_off);
}